// round 1
// baseline (speedup 1.0000x reference)
#include <cuda_runtime.h>
#include <math.h>

#define Hh 512
#define Ww 512
#define Ss 5
#define Cin 2
#define Cout 2
#define TW 32
#define TH 8
#define NPLANES (Ss*Cin)           // 10
#define TILE_W (TW+2)              // 34
#define TILE_H (TH+2)              // 10
#define PLANE_ELEMS (TILE_W*TILE_H)

__global__ __launch_bounds__(256, 4)
void snn_fused_kernel(const float* __restrict__ in,
                      const float* __restrict__ conv_w,
                      const float* __restrict__ conv_b,
                      const float* __restrict__ gamma,
                      const float* __restrict__ beta_bn,
                      const float* __restrict__ run_mean,
                      const float* __restrict__ run_var,
                      const float* __restrict__ rho,
                      float* __restrict__ out)
{
    __shared__ float sw[Cout*Cin*9];   // folded weights
    __shared__ float sb[Cout];         // folded bias
    __shared__ float sad[Cout];        // a_decay
    __shared__ float tile[NPLANES][TILE_H][TILE_W];

    const int tx  = threadIdx.x;           // 0..31
    const int ty  = threadIdx.y;           // 0..7
    const int tid = ty * 32 + tx;
    const int b      = blockIdx.z;
    const int h_base = blockIdx.y * TH;
    const int w_base = blockIdx.x * TW;

    // ---- fold BN into conv weights/bias; precompute a_decay ----
    if (tid < Cout*Cin*9) {
        int o = tid / (Cin*9);
        float inv = gamma[o] * rsqrtf(run_var[o] + 1e-5f);
        sw[tid] = conv_w[tid] * inv;
    }
    if (tid < Cout) {
        float inv = gamma[tid] * rsqrtf(run_var[tid] + 1e-5f);
        sb[tid]  = (conv_b[tid] - run_mean[tid]) * inv + beta_bn[tid];
        float rc = fminf(fmaxf(rho[tid], 0.032f), 0.055f);
        sad[tid] = expf(-0.05f / rc);
    }

    // ---- cooperative load of 10 (s,c) planes with zero-padded halo ----
    const size_t img = (size_t)Hh * Ww;
    #pragma unroll 4
    for (int idx = tid; idx < NPLANES * PLANE_ELEMS; idx += 256) {
        int p   = idx / PLANE_ELEMS;
        int r   = idx - p * PLANE_ELEMS;
        int row = r / TILE_W;
        int col = r - row * TILE_W;
        int gh = h_base + row - 1;
        int gw = w_base + col - 1;
        float v = 0.0f;
        if ((unsigned)gh < Hh && (unsigned)gw < Ww) {
            int s = p >> 1;
            int c = p & 1;
            v = in[((size_t)((b*Ss + s)*Cin + c)) * img + (size_t)gh * Ww + gw];
        }
        tile[p][row][col] = v;
    }
    __syncthreads();

    // ---- conv: 5 steps x 2 out channels per thread ----
    float acc[Ss][Cout];
    #pragma unroll
    for (int s = 0; s < Ss; s++) { acc[s][0] = 0.0f; acc[s][1] = 0.0f; }

    #pragma unroll
    for (int s = 0; s < Ss; s++) {
        #pragma unroll
        for (int c = 0; c < Cin; c++) {
            const int p = s*2 + c;
            float v00 = tile[p][ty+0][tx+0];
            float v01 = tile[p][ty+0][tx+1];
            float v02 = tile[p][ty+0][tx+2];
            float v10 = tile[p][ty+1][tx+0];
            float v11 = tile[p][ty+1][tx+1];
            float v12 = tile[p][ty+1][tx+2];
            float v20 = tile[p][ty+2][tx+0];
            float v21 = tile[p][ty+2][tx+1];
            float v22 = tile[p][ty+2][tx+2];
            #pragma unroll
            for (int o = 0; o < Cout; o++) {
                const float* w = &sw[(o*Cin + c) * 9];
                float a0 = acc[s][o];
                a0 = fmaf(v00, w[0], a0);
                a0 = fmaf(v01, w[1], a0);
                a0 = fmaf(v02, w[2], a0);
                a0 = fmaf(v10, w[3], a0);
                a0 = fmaf(v11, w[4], a0);
                a0 = fmaf(v12, w[5], a0);
                a0 = fmaf(v20, w[6], a0);
                a0 = fmaf(v21, w[7], a0);
                a0 = fmaf(v22, w[8], a0);
                acc[s][o] = a0;
            }
        }
    }

    // ---- LSNN recurrence + write spikes ----
    const int h0 = h_base + ty;
    const int w0 = w_base + tx;
    const size_t pix = (size_t)h0 * Ww + w0;

    #pragma unroll
    for (int o = 0; o < Cout; o++) {
        float mem = 0.0f, a = 0.0f;
        const float ad = sad[o];
        const float bias = sb[o];
        #pragma unroll
        for (int s = 0; s < Ss; s++) {
            float A = 0.3f + 0.07f * a;
            mem += acc[s][o] + bias;
            float spike = (mem > A) ? 1.0f : 0.0f;
            mem = mem * 0.2f * (1.0f - spike);
            a = ad * a + spike;
            out[((size_t)((b*Ss + s)*Cout + o)) * img + pix] = spike;
        }
    }
}

extern "C" void kernel_launch(void* const* d_in, const int* in_sizes, int n_in,
                              void* d_out, int out_size)
{
    const float* all_input = (const float*)d_in[0];
    const float* conv_w    = (const float*)d_in[1];
    const float* conv_b    = (const float*)d_in[2];
    const float* gamma     = (const float*)d_in[3];
    const float* beta_bn   = (const float*)d_in[4];
    const float* run_mean  = (const float*)d_in[5];
    const float* run_var   = (const float*)d_in[6];
    const float* rho       = (const float*)d_in[7];
    float* out = (float*)d_out;

    dim3 block(32, 8, 1);
    dim3 grid(Ww / TW, Hh / TH, 16);   // 16 x 64 x 16 = 16384 blocks
    snn_fused_kernel<<<grid, block>>>(all_input, conv_w, conv_b, gamma, beta_bn,
                                      run_mean, run_var, rho, out);
}

// round 2
// speedup vs baseline: 2.8178x; 2.8178x over previous
#include <cuda_runtime.h>
#include <math.h>

#define Hh 512
#define Ww 512
#define Ss 5
#define Cin 2
#define Cout 2

#define TW 128           // output tile width per block
#define TH 8             // output tile height per block
#define ROWS (TH + 2)    // 10 input rows incl. halo
#define NPLANES 10       // S*C planes
#define RSTRIDE 136      // floats per smem row (interior at +4, halos at 3 and 132)
#define PLANE (ROWS * RSTRIDE)
#define SMEM_BYTES (NPLANES * PLANE * 4)   // 54400

extern __shared__ float tile[];   // [plane][row][RSTRIDE], col j=4+k <-> w_base+k

__global__ __launch_bounds__(256, 2)
void snn_fused2(const float* __restrict__ in,
                const float* __restrict__ conv_w,
                const float* __restrict__ conv_b,
                const float* __restrict__ gamma,
                const float* __restrict__ beta_bn,
                const float* __restrict__ run_mean,
                const float* __restrict__ run_var,
                const float* __restrict__ rho,
                float* __restrict__ out)
{
    __shared__ float sw[Cout * Cin * 9];
    __shared__ float sb[Cout];
    __shared__ float sad[Cout];

    const int tx  = threadIdx.x;          // 0..31
    const int ty  = threadIdx.y;          // 0..7
    const int tid = ty * 32 + tx;
    const int b      = blockIdx.z;
    const int h_base = blockIdx.y * TH;
    const int w_base = blockIdx.x * TW;

    // ---- fold BN into weights/bias, precompute adaptation decay ----
    if (tid < Cout * Cin * 9) {
        int o = tid / (Cin * 9);
        sw[tid] = conv_w[tid] * (gamma[o] * rsqrtf(run_var[o] + 1e-5f));
    }
    if (tid < Cout) {
        float inv = gamma[tid] * rsqrtf(run_var[tid] + 1e-5f);
        sb[tid]  = (conv_b[tid] - run_mean[tid]) * inv + beta_bn[tid];
        float rc = fminf(fmaxf(rho[tid], 0.032f), 0.055f);
        sad[tid] = expf(-0.05f / rc);
    }

    const size_t img = (size_t)Hh * Ww;
    const float* bin = in + (size_t)b * NPLANES * img;   // plane p = s*2+c contiguous

    // ---- cooperative interior load: 10 planes x 10 rows x 32 float4 ----
    #pragma unroll 4
    for (int i = tid; i < NPLANES * ROWS * 32; i += 256) {
        int f4  = i & 31;
        int t   = i >> 5;            // 0..99
        int row = t % ROWS;
        int p   = t / ROWS;
        int gh  = h_base + row - 1;
        float4 v = make_float4(0.f, 0.f, 0.f, 0.f);
        if ((unsigned)gh < (unsigned)Hh) {
            v = *(const float4*)(bin + (size_t)p * img + (size_t)gh * Ww + w_base + f4 * 4);
        }
        *(float4*)&tile[p * PLANE + row * RSTRIDE + 4 + f4 * 4] = v;
    }

    // ---- halo columns: j=3 (w_base-1), j=132 (w_base+128) ----
    if (tid < NPLANES * ROWS * 2) {
        int p    = tid / (ROWS * 2);
        int rr   = tid - p * (ROWS * 2);
        int row  = rr >> 1;
        int side = rr & 1;
        int gh = h_base + row - 1;
        int gw = side ? (w_base + TW) : (w_base - 1);
        float v = 0.f;
        if ((unsigned)gh < (unsigned)Hh && (unsigned)gw < (unsigned)Ww) {
            v = bin[(size_t)p * img + (size_t)gh * Ww + gw];
        }
        tile[p * PLANE + row * RSTRIDE + (side ? 132 : 3)] = v;
    }
    __syncthreads();

    // ---- conv: 4 px/thread, 5 steps x 2 out-channels ----
    float acc[Ss][Cout][4];
    #pragma unroll
    for (int s = 0; s < Ss; s++)
        #pragma unroll
        for (int o = 0; o < Cout; o++)
            #pragma unroll
            for (int k = 0; k < 4; k++) acc[s][o][k] = 0.f;

    const int P = 4 * tx;    // local px base; window j = P+3 .. P+8

    #pragma unroll
    for (int p = 0; p < NPLANES; p++) {
        const int s = p >> 1;
        const int c = p & 1;
        const float* pl = &tile[p * PLANE + ty * RSTRIDE + P];
        #pragma unroll
        for (int r = 0; r < 3; r++) {
            const float* rp = pl + r * RSTRIDE;
            float4 A4 = *(const float4*)(rp);       // need .w (= w-1)
            float4 B4 = *(const float4*)(rp + 4);   // w..w+3
            float4 C4 = *(const float4*)(rp + 8);   // need .x (= w+4)
            float vv[6];
            vv[0] = A4.w; vv[1] = B4.x; vv[2] = B4.y;
            vv[3] = B4.z; vv[4] = B4.w; vv[5] = C4.x;
            #pragma unroll
            for (int o = 0; o < Cout; o++) {
                const float* w = &sw[(o * Cin + c) * 9 + r * 3];
                float w0 = w[0], w1 = w[1], w2 = w[2];
                #pragma unroll
                for (int k = 0; k < 4; k++) {
                    float a0 = acc[s][o][k];
                    a0 = fmaf(vv[k],     w0, a0);
                    a0 = fmaf(vv[k + 1], w1, a0);
                    a0 = fmaf(vv[k + 2], w2, a0);
                    acc[s][o][k] = a0;
                }
            }
        }
    }

    // ---- LSNN recurrence + vector spike stores ----
    const int h0 = h_base + ty;
    const size_t opix = (size_t)h0 * Ww + w_base + P;

    float mem[Cout][4], aa[Cout][4];
    #pragma unroll
    for (int o = 0; o < Cout; o++)
        #pragma unroll
        for (int k = 0; k < 4; k++) { mem[o][k] = 0.f; aa[o][k] = 0.f; }

    #pragma unroll
    for (int s = 0; s < Ss; s++) {
        #pragma unroll
        for (int o = 0; o < Cout; o++) {
            float spk[4];
            const float bias = sb[o];
            const float ad   = sad[o];
            #pragma unroll
            for (int k = 0; k < 4; k++) {
                float Ath = 0.3f + 0.07f * aa[o][k];
                float m = mem[o][k] + acc[s][o][k] + bias;
                float sv = (m > Ath) ? 1.f : 0.f;
                mem[o][k] = m * 0.2f * (1.f - sv);
                aa[o][k] = ad * aa[o][k] + sv;
                spk[k] = sv;
            }
            *(float4*)(out + ((size_t)(b * 10 + s * 2 + o)) * img + opix) =
                make_float4(spk[0], spk[1], spk[2], spk[3]);
        }
    }
}

extern "C" void kernel_launch(void* const* d_in, const int* in_sizes, int n_in,
                              void* d_out, int out_size)
{
    const float* all_input = (const float*)d_in[0];
    const float* conv_w    = (const float*)d_in[1];
    const float* conv_b    = (const float*)d_in[2];
    const float* gamma     = (const float*)d_in[3];
    const float* beta_bn   = (const float*)d_in[4];
    const float* run_mean  = (const float*)d_in[5];
    const float* run_var   = (const float*)d_in[6];
    const float* rho       = (const float*)d_in[7];
    float* out = (float*)d_out;

    cudaFuncSetAttribute(snn_fused2,
                         cudaFuncAttributeMaxDynamicSharedMemorySize, SMEM_BYTES);

    dim3 block(32, 8, 1);
    dim3 grid(Ww / TW, Hh / TH, 16);   // 4 x 64 x 16 = 4096 blocks
    snn_fused2<<<grid, block, SMEM_BYTES>>>(all_input, conv_w, conv_b, gamma, beta_bn,
                                            run_mean, run_var, rho, out);
}

// round 3
// speedup vs baseline: 2.8777x; 1.0213x over previous
#include <cuda_runtime.h>
#include <math.h>

#define Hh 512
#define Ww 512
#define Ss 5
#define Cin 2
#define Cout 2

#define TW 128
#define TH 8
#define ROWS (TH + 2)     // 10
#define NPLANES 10
#define RSTRIDE 136       // interior cols at 4..131, halos at 3 and 132
#define PLANE (ROWS * RSTRIDE)
#define SMEM_BYTES (NPLANES * PLANE * 4)   // 54400

extern __shared__ float tile[];

__global__ __launch_bounds__(256, 4)
void snn_fused3(const float* __restrict__ in,
                const float* __restrict__ conv_w,
                const float* __restrict__ conv_b,
                const float* __restrict__ gamma,
                const float* __restrict__ beta_bn,
                const float* __restrict__ run_mean,
                const float* __restrict__ run_var,
                const float* __restrict__ rho,
                float* __restrict__ out)
{
    __shared__ float sw[Cout * Cin * 9];
    __shared__ float sb[Cout];
    __shared__ float sad[Cout];

    const int tx  = threadIdx.x;          // 0..31
    const int ty  = threadIdx.y;          // 0..7
    const int tid = ty * 32 + tx;
    const int b      = blockIdx.z;
    const int h_base = blockIdx.y * TH;
    const int w_base = blockIdx.x * TW;

    if (tid < Cout * Cin * 9) {
        int o = tid / (Cin * 9);
        sw[tid] = conv_w[tid] * (gamma[o] * rsqrtf(run_var[o] + 1e-5f));
    }
    if (tid < Cout) {
        float inv = gamma[tid] * rsqrtf(run_var[tid] + 1e-5f);
        sb[tid]  = (conv_b[tid] - run_mean[tid]) * inv + beta_bn[tid];
        float rc = fminf(fmaxf(rho[tid], 0.032f), 0.055f);
        sad[tid] = expf(-0.05f / rc);
    }

    const size_t img = (size_t)Hh * Ww;
    const float* bin = in + (size_t)b * NPLANES * img;

    // ---- cooperative interior fill: 10 planes x 10 rows x 32 float4 ----
    #pragma unroll 4
    for (int i = tid; i < NPLANES * ROWS * 32; i += 256) {
        int f4  = i & 31;
        int t   = i >> 5;
        int row = t % ROWS;
        int p   = t / ROWS;
        int gh  = h_base + row - 1;
        float4 v = make_float4(0.f, 0.f, 0.f, 0.f);
        if ((unsigned)gh < (unsigned)Hh) {
            v = *(const float4*)(bin + (size_t)p * img + (size_t)gh * Ww + w_base + f4 * 4);
        }
        *(float4*)&tile[p * PLANE + row * RSTRIDE + 4 + f4 * 4] = v;
    }
    // ---- halo columns ----
    if (tid < NPLANES * ROWS * 2) {
        int p    = tid / (ROWS * 2);
        int rr   = tid - p * (ROWS * 2);
        int row  = rr >> 1;
        int side = rr & 1;
        int gh = h_base + row - 1;
        int gw = side ? (w_base + TW) : (w_base - 1);
        float v = 0.f;
        if ((unsigned)gh < (unsigned)Hh && (unsigned)gw < (unsigned)Ww) {
            v = bin[(size_t)p * img + (size_t)gh * Ww + gw];
        }
        tile[p * PLANE + row * RSTRIDE + (side ? 132 : 3)] = v;
    }
    __syncthreads();

    const int P = 4 * tx;
    const int h0 = h_base + ty;
    const size_t opix = (size_t)h0 * Ww + w_base + P;

    float mem[Cout][4], aa[Cout][4];
    #pragma unroll
    for (int o = 0; o < Cout; o++)
        #pragma unroll
        for (int k = 0; k < 4; k++) { mem[o][k] = 0.f; aa[o][k] = 0.f; }

    #pragma unroll
    for (int s = 0; s < Ss; s++) {
        float acc[Cout][4];
        #pragma unroll
        for (int o = 0; o < Cout; o++)
            #pragma unroll
            for (int k = 0; k < 4; k++) acc[o][k] = 0.f;

        #pragma unroll
        for (int c = 0; c < Cin; c++) {
            const int p = s * 2 + c;
            const float* pl = &tile[p * PLANE + ty * RSTRIDE];
            #pragma unroll
            for (int r = 0; r < 3; r++) {
                const float* rp = pl + r * RSTRIDE;
                float4 B4 = *(const float4*)(rp + 4 + P);     // cols P+4..P+7 (aligned)
                float left  = __shfl_up_sync(0xffffffffu, B4.w, 1);   // col P+3
                float right = __shfl_down_sync(0xffffffffu, B4.x, 1); // col P+8
                if (tx == 0)  left  = rp[3];
                if (tx == 31) right = rp[132];
                float vv0 = left, vv1 = B4.x, vv2 = B4.y,
                      vv3 = B4.z, vv4 = B4.w, vv5 = right;
                #pragma unroll
                for (int o = 0; o < Cout; o++) {
                    const float* w = &sw[(o * Cin + c) * 9 + r * 3];
                    float w0 = w[0], w1 = w[1], w2 = w[2];
                    float a0 = acc[o][0], a1 = acc[o][1], a2 = acc[o][2], a3 = acc[o][3];
                    a0 = fmaf(vv0, w0, a0); a0 = fmaf(vv1, w1, a0); a0 = fmaf(vv2, w2, a0);
                    a1 = fmaf(vv1, w0, a1); a1 = fmaf(vv2, w1, a1); a1 = fmaf(vv3, w2, a1);
                    a2 = fmaf(vv2, w0, a2); a2 = fmaf(vv3, w1, a2); a2 = fmaf(vv4, w2, a2);
                    a3 = fmaf(vv3, w0, a3); a3 = fmaf(vv4, w1, a3); a3 = fmaf(vv5, w2, a3);
                    acc[o][0] = a0; acc[o][1] = a1; acc[o][2] = a2; acc[o][3] = a3;
                }
            }
        }

        // recurrence for this step + streaming store
        #pragma unroll
        for (int o = 0; o < Cout; o++) {
            const float bias = sb[o];
            const float ad   = sad[o];
            float spk[4];
            #pragma unroll
            for (int k = 0; k < 4; k++) {
                float Ath = 0.3f + 0.07f * aa[o][k];
                float m = mem[o][k] + acc[o][k] + bias;
                float sv = (m > Ath) ? 1.f : 0.f;
                mem[o][k] = m * 0.2f * (1.f - sv);
                aa[o][k] = ad * aa[o][k] + sv;
                spk[k] = sv;
            }
            float4 v4 = make_float4(spk[0], spk[1], spk[2], spk[3]);
            __stcs((float4*)(out + ((size_t)(b * 10 + s * 2 + o)) * img + opix), v4);
        }
    }
}

extern "C" void kernel_launch(void* const* d_in, const int* in_sizes, int n_in,
                              void* d_out, int out_size)
{
    const float* all_input = (const float*)d_in[0];
    const float* conv_w    = (const float*)d_in[1];
    const float* conv_b    = (const float*)d_in[2];
    const float* gamma     = (const float*)d_in[3];
    const float* beta_bn   = (const float*)d_in[4];
    const float* run_mean  = (const float*)d_in[5];
    const float* run_var   = (const float*)d_in[6];
    const float* rho       = (const float*)d_in[7];
    float* out = (float*)d_out;

    cudaFuncSetAttribute(snn_fused3,
                         cudaFuncAttributeMaxDynamicSharedMemorySize, SMEM_BYTES);

    dim3 block(32, 8, 1);
    dim3 grid(Ww / TW, Hh / TH, 16);   // 4 x 64 x 16 = 4096 blocks
    snn_fused3<<<grid, block, SMEM_BYTES>>>(all_input, conv_w, conv_b, gamma, beta_bn,
                                            run_mean, run_var, rho, out);
}